// round 2
// baseline (speedup 1.0000x reference)
#include <cuda_runtime.h>
#include <stdint.h>

// Problem constants (fixed by reference setup_inputs)
#define MAX_ATOMS 500000
#define MAX_MOL   5000

// Scratch (no cudaMalloc allowed)
__device__ float g_qmol[MAX_MOL];
__device__ float g_qic[MAX_ATOMS];

// ---------------- zero out + qmol ----------------
__global__ void zero_kernel(float* __restrict__ out, int n_atoms, int n_mol) {
    int i = blockIdx.x * blockDim.x + threadIdx.x;
    if (i < n_atoms) out[i] = 0.0f;
    if (i < n_mol)   g_qmol[i] = 0.0f;
}

// ---------------- q_mol = segment_sum(qi, batch) ----------------
// atom_mol_batch is sorted; aggregate 4 consecutive atoms when same mol.
__global__ void qmol_kernel(const float* __restrict__ qi,
                            const int* __restrict__ batch, int n_atoms) {
    int t = blockIdx.x * blockDim.x + threadIdx.x;
    int i = t * 4;
    if (i + 3 < n_atoms) {
        float4 q = *reinterpret_cast<const float4*>(qi + i);
        int4   b = *reinterpret_cast<const int4*>(batch + i);
        if (b.x == b.y && b.x == b.z && b.x == b.w) {
            atomicAdd(&g_qmol[b.x], q.x + q.y + q.z + q.w);
        } else {
            atomicAdd(&g_qmol[b.x], q.x);
            atomicAdd(&g_qmol[b.y], q.y);
            atomicAdd(&g_qmol[b.z], q.z);
            atomicAdd(&g_qmol[b.w], q.w);
        }
    } else {
        for (int k = i; k < n_atoms; k++)
            atomicAdd(&g_qmol[batch[k]], qi[k]);
    }
}

// ---------------- qi_c = qi - (q_mol - q_ref)/N ----------------
__global__ void qic_kernel(const float* __restrict__ qi,
                           const int* __restrict__ batch,
                           const float* __restrict__ q_ref,
                           const int* __restrict__ Nv, int n_atoms) {
    int i = blockIdx.x * blockDim.x + threadIdx.x;
    if (i < n_atoms) {
        int b = batch[i];
        float corr = (g_qmol[b] - q_ref[b]) / (float)Nv[b];
        g_qic[i] = qi[i] - corr;
    }
}

// ---------------- per-edge Coulomb with scatter-add ----------------
__device__ __forceinline__ float chi_term(float r) {
    // phi = 1/sqrt(r^2+1); f = cutoff_fn(2r, 10) i.e. x = r/5
    float phi   = rsqrtf(fmaf(r, r, 1.0f));
    float inv_r = __fdividef(1.0f, r);
    float x  = r * 0.2f;                 // 2r / CUTOFF
    float chi;
    if (x < 1.0f) {
        float x3 = x * x * x;
        // f = 1 - 6x^5 + 15x^4 - 10x^3 = 1 + x^3*(-10 + x*(15 - 6x))
        float f = fmaf(x3, fmaf(x, fmaf(x, -6.0f, 15.0f), -10.0f), 1.0f);
        chi = f * phi + (1.0f - f) * inv_r;
    } else {
        chi = inv_r;
    }
    return chi;
}

__global__ void __launch_bounds__(256)
edge_kernel(const float* __restrict__ dist,
            const int* __restrict__ idx0,
            const int* __restrict__ idx1,
            float* __restrict__ out, int n_edges) {
    int t = blockIdx.x * blockDim.x + threadIdx.x;
    int e = t * 4;
    if (e + 3 < n_edges) {
        float4 d = *reinterpret_cast<const float4*>(dist + e);
        int4   a = *reinterpret_cast<const int4*>(idx0 + e);
        int4   b = *reinterpret_cast<const int4*>(idx1 + e);

        float t0 = __ldg(&g_qic[a.x]) * __ldg(&g_qic[b.x]) * chi_term(d.x);
        float t1 = __ldg(&g_qic[a.y]) * __ldg(&g_qic[b.y]) * chi_term(d.y);
        float t2 = __ldg(&g_qic[a.z]) * __ldg(&g_qic[b.z]) * chi_term(d.z);
        float t3 = __ldg(&g_qic[a.w]) * __ldg(&g_qic[b.w]) * chi_term(d.w);

        atomicAdd(&out[a.x], 0.5f * t0);
        atomicAdd(&out[a.y], 0.5f * t1);
        atomicAdd(&out[a.z], 0.5f * t2);
        atomicAdd(&out[a.w], 0.5f * t3);
    } else {
        for (int k = e; k < n_edges; k++) {
            float r = dist[k];
            int ia = idx0[k], ib = idx1[k];
            float term = g_qic[ia] * g_qic[ib] * chi_term(r);
            atomicAdd(&out[ia], 0.5f * term);
        }
    }
}

extern "C" void kernel_launch(void* const* d_in, const int* in_sizes, int n_in,
                              void* d_out, int out_size) {
    const float* qi       = (const float*)d_in[0];
    const float* dist     = (const float*)d_in[1];
    const int*   eidx     = (const int*)d_in[2];
    const float* q_ref    = (const float*)d_in[3];
    const int*   Nv       = (const int*)d_in[4];
    const int*   batch    = (const int*)d_in[5];
    float*       out      = (float*)d_out;

    int n_atoms = in_sizes[0];
    int n_edges = in_sizes[1];
    int n_mol   = in_sizes[3];

    const int* idx0 = eidx;
    const int* idx1 = eidx + n_edges;

    {
        int tpb = 256;
        zero_kernel<<<(n_atoms + tpb - 1) / tpb, tpb>>>(out, n_atoms, n_mol);
    }
    {
        int tpb = 256;
        int nthreads = (n_atoms + 3) / 4;
        qmol_kernel<<<(nthreads + tpb - 1) / tpb, tpb>>>(qi, batch, n_atoms);
    }
    {
        int tpb = 256;
        qic_kernel<<<(n_atoms + tpb - 1) / tpb, tpb>>>(qi, batch, q_ref, Nv, n_atoms);
    }
    {
        int tpb = 256;
        int nthreads = (n_edges + 3) / 4;
        edge_kernel<<<(nthreads + tpb - 1) / tpb, tpb>>>(dist, idx0, idx1, out, n_edges);
    }
}

// round 4
// speedup vs baseline: 1.2944x; 1.2944x over previous
#include <cuda_runtime.h>
#include <stdint.h>

// Problem constants (fixed by reference setup_inputs)
#define MAX_ATOMS 500000
#define MAX_MOL   5000

// Scratch (no cudaMalloc allowed)
__device__ float g_qmol[MAX_MOL];
__device__ float g_qic[MAX_ATOMS];
__device__ float g_S[MAX_ATOMS];     // S[a] = sum over edges(idx0=a) of q_j * chi(r)

// ---------------- K1: zero S + qmol ----------------
__global__ void zero_kernel(int n_atoms, int n_mol) {
    int i = blockIdx.x * blockDim.x + threadIdx.x;
    if (i < n_atoms) g_S[i] = 0.0f;
    if (i < n_mol)   g_qmol[i] = 0.0f;
}

// ---------------- K2: q_mol = segment_sum(qi, batch) ----------------
// atom_mol_batch is sorted; aggregate 4 consecutive atoms when same mol.
__global__ void qmol_kernel(const float* __restrict__ qi,
                            const int* __restrict__ batch, int n_atoms) {
    int t = blockIdx.x * blockDim.x + threadIdx.x;
    int i = t * 4;
    if (i + 3 < n_atoms) {
        float4 q = *reinterpret_cast<const float4*>(qi + i);
        int4   b = *reinterpret_cast<const int4*>(batch + i);
        if (b.x == b.y && b.x == b.z && b.x == b.w) {
            atomicAdd(&g_qmol[b.x], q.x + q.y + q.z + q.w);
        } else {
            atomicAdd(&g_qmol[b.x], q.x);
            atomicAdd(&g_qmol[b.y], q.y);
            atomicAdd(&g_qmol[b.z], q.z);
            atomicAdd(&g_qmol[b.w], q.w);
        }
    } else {
        for (int k = i; k < n_atoms; k++)
            atomicAdd(&g_qmol[batch[k]], qi[k]);
    }
}

// ---------------- K3: qi_c = qi - (q_mol - q_ref)/N ----------------
__global__ void qic_kernel(const float* __restrict__ qi,
                           const int* __restrict__ batch,
                           const float* __restrict__ q_ref,
                           const int* __restrict__ Nv, int n_atoms) {
    int i = blockIdx.x * blockDim.x + threadIdx.x;
    if (i < n_atoms) {
        int b = batch[i];
        float corr = (g_qmol[b] - q_ref[b]) / (float)Nv[b];
        g_qic[i] = qi[i] - corr;
    }
}

// ---------------- chi(r) ----------------
__device__ __forceinline__ float chi_term(float r) {
    // phi = 1/sqrt(r^2+1); f = cutoff_fn(2r, 10) i.e. x = r/5
    float phi   = rsqrtf(fmaf(r, r, 1.0f));
    float inv_r = __fdividef(1.0f, r);
    float x  = r * 0.2f;                 // 2r / CUTOFF
    float chi;
    if (x < 1.0f) {
        float x3 = x * x * x;
        // f = 1 - 6x^5 + 15x^4 - 10x^3 = 1 + x^3*(-10 + x*(15 - 6x))
        float f = fmaf(x3, fmaf(x, fmaf(x, -6.0f, 15.0f), -10.0f), 1.0f);
        chi = f * phi + (1.0f - f) * inv_r;
    } else {
        chi = inv_r;
    }
    return chi;
}

// ---------------- K4: edge loop, accumulate S[a] += q_j * chi(r) ----------------
// 2 random accesses/edge (gather q_j, red.add S[a]); q_i factored out.
__global__ void __launch_bounds__(256)
edge_kernel(const float* __restrict__ dist,
            const int* __restrict__ idx0,
            const int* __restrict__ idx1, int n_edges) {
    int t = blockIdx.x * blockDim.x + threadIdx.x;
    int e = t * 4;
    if (e + 3 < n_edges) {
        float4 d = *reinterpret_cast<const float4*>(dist + e);
        int4   a = *reinterpret_cast<const int4*>(idx0 + e);
        int4   b = *reinterpret_cast<const int4*>(idx1 + e);

        float t0 = __ldg(&g_qic[b.x]) * chi_term(d.x);
        float t1 = __ldg(&g_qic[b.y]) * chi_term(d.y);
        float t2 = __ldg(&g_qic[b.z]) * chi_term(d.z);
        float t3 = __ldg(&g_qic[b.w]) * chi_term(d.w);

        atomicAdd(&g_S[a.x], t0);
        atomicAdd(&g_S[a.y], t1);
        atomicAdd(&g_S[a.z], t2);
        atomicAdd(&g_S[a.w], t3);
    } else {
        for (int k = e; k < n_edges; k++) {
            float r = dist[k];
            float term = g_qic[idx1[k]] * chi_term(r);
            atomicAdd(&g_S[idx0[k]], term);
        }
    }
}

// ---------------- K5: out = 0.5 * qi_c * S ----------------
__global__ void finish_kernel(float* __restrict__ out, int n_atoms) {
    int t = blockIdx.x * blockDim.x + threadIdx.x;
    int i = t * 4;
    if (i + 3 < n_atoms) {
        float4 q = *reinterpret_cast<const float4*>(g_qic + i);
        float4 s = *reinterpret_cast<const float4*>(g_S + i);
        float4 o;
        o.x = 0.5f * q.x * s.x;
        o.y = 0.5f * q.y * s.y;
        o.z = 0.5f * q.z * s.z;
        o.w = 0.5f * q.w * s.w;
        *reinterpret_cast<float4*>(out + i) = o;
    } else {
        for (int k = i; k < n_atoms; k++)
            out[k] = 0.5f * g_qic[k] * g_S[k];
    }
}

extern "C" void kernel_launch(void* const* d_in, const int* in_sizes, int n_in,
                              void* d_out, int out_size) {
    const float* qi       = (const float*)d_in[0];
    const float* dist     = (const float*)d_in[1];
    const int*   eidx     = (const int*)d_in[2];
    const float* q_ref    = (const float*)d_in[3];
    const int*   Nv       = (const int*)d_in[4];
    const int*   batch    = (const int*)d_in[5];
    float*       out      = (float*)d_out;

    int n_atoms = in_sizes[0];
    int n_edges = in_sizes[1];
    int n_mol   = in_sizes[3];

    const int* idx0 = eidx;
    const int* idx1 = eidx + n_edges;

    const int tpb = 256;
    zero_kernel<<<(n_atoms + tpb - 1) / tpb, tpb>>>(n_atoms, n_mol);

    {
        int nthreads = (n_atoms + 3) / 4;
        qmol_kernel<<<(nthreads + tpb - 1) / tpb, tpb>>>(qi, batch, n_atoms);
    }
    qic_kernel<<<(n_atoms + tpb - 1) / tpb, tpb>>>(qi, batch, q_ref, Nv, n_atoms);

    {
        int nthreads = (n_edges + 3) / 4;
        edge_kernel<<<(nthreads + tpb - 1) / tpb, tpb>>>(dist, idx0, idx1, n_edges);
    }
    {
        int nthreads = (n_atoms + 3) / 4;
        finish_kernel<<<(nthreads + tpb - 1) / tpb, tpb>>>(out, n_atoms);
    }
}